// round 11
// baseline (speedup 1.0000x reference)
#include <cuda_runtime.h>
#include <math.h>

#define Mm 3
#define Bb 32
#define Ss 256
#define Dd 768
#define D4 192
#define Hh 1024
#define NPAIR 6
#define LNEPS 1e-5f
#define SCALE 0.036084391824351615f

// ---------------- scratch (__device__ globals) ------------
__device__ __align__(16) float g_wmu[Mm][Dd], g_wlv[Mm][Dd], g_wpq[Mm][Dd]; // atomic accum
__device__ float g_cmu[Mm], g_clv[Mm];
__device__ __align__(16) float g_wpk[Mm][Mm][Dd];                            // atomic accum
__device__ float g_cpk[Mm][Mm];
__device__ __align__(16) float g_Q0[Mm][Bb][Dd];          // atomic accum
__device__ __align__(16) float g_qkvec[Mm][Mm][Bb][Dd];   // atomic accum
__device__ float g_qbk[Mm][Mm][Bb];
__device__ float g_pq0[Mm][Bb];                            // pq logit at s=0
__device__ float g_mu[Mm][Bb][Ss], g_lv[Mm][Bb][Ss];
__device__ float g_kd[Mm][Mm][Bb][Ss];
__device__ float g_dotA[Mm][Mm][Bb][Ss];
__device__ __align__(16) float g_wf[Mm][Mm][Bb][Dd];
__device__ __align__(16) float g_agg[Mm][Bb][Dd];         // atomic accum
__device__ __align__(16) float g_E[Mm][Bb][Dd], g_G[Mm][Bb][Dd]; // atomic accum
__device__ __align__(16) float g_C[Mm][Bb][Dd];
__device__ float g_kl;

__device__ __forceinline__ float warp_sum(float v){
    #pragma unroll
    for(int o=16;o>0;o>>=1) v += __shfl_down_sync(0xffffffffu, v, o);
    return v;
}
__device__ __forceinline__ float sigmoidf(float x){ return 1.f/(1.f+expf(-x)); }
__device__ __forceinline__ float dot4(float4 a, float4 b){
    return a.x*b.x + a.y*b.y + a.z*b.z + a.w*b.w;
}

// ======== kernel 1: zero accumulators + scalar constants ========
__global__ void k_init(const float* __restrict__ bq, const float* __restrict__ bk,
                       const float* __restrict__ mu_w, const float* __restrict__ mu_b,
                       const float* __restrict__ lv_w, const float* __restrict__ lv_b,
                       const float* __restrict__ pgq_w, const float* __restrict__ pgq_b,
                       const float* __restrict__ pgk_w, const float* __restrict__ pgk_b){
    if(blockIdx.x < 160){
        int tid = blockIdx.x*256 + threadIdx.x;
        const int stride = 160*256;
        float* p;
        p=&g_Q0[0][0][0];       for(int i=tid;i<Mm*Bb*Dd;i+=stride)    p[i]=0.f;
        p=&g_qkvec[0][0][0][0]; for(int i=tid;i<Mm*Mm*Bb*Dd;i+=stride) p[i]=0.f;
        p=&g_agg[0][0][0];      for(int i=tid;i<Mm*Bb*Dd;i+=stride)    p[i]=0.f;
        p=&g_E[0][0][0];        for(int i=tid;i<Mm*Bb*Dd;i+=stride)    p[i]=0.f;
        p=&g_G[0][0][0];        for(int i=tid;i<Mm*Bb*Dd;i+=stride)    p[i]=0.f;
        p=&g_wmu[0][0];         for(int i=tid;i<Mm*Dd;i+=stride)       p[i]=0.f;
        p=&g_wlv[0][0];         for(int i=tid;i<Mm*Dd;i+=stride)       p[i]=0.f;
        p=&g_wpq[0][0];         for(int i=tid;i<Mm*Dd;i+=stride)       p[i]=0.f;
        p=&g_wpk[0][0][0];      for(int i=tid;i<Mm*Mm*Dd;i+=stride)    p[i]=0.f;
        if(tid==0) g_kl=0.f;
    } else {
        int wid=threadIdx.x>>5, lane=threadIdx.x&31;
        for(int t=wid;t<15;t+=8){
            if(t<6){
                int m=t/2, which=t%2;
                const float* wv = (which==0)? mu_w : lv_w;
                float a=0.f;
                for(int e=lane;e<Dd;e+=32) a += bq[m*Dd+e]*wv[m*Dd+e];
                a=warp_sum(a);
                if(!lane){
                    if(which==0) g_cmu[m]=a+mu_b[m];
                    else g_clv[m]=a+lv_b[m];
                }
            } else {
                int q=t-6; int i=q/3, j=q%3;
                float a=0.f;
                for(int e=lane;e<Dd;e+=32) a += bk[j*Dd+e]*pgk_w[i*Dd+e];
                a=warp_sum(a);
                if(!lane) g_cpk[i][j]=a+pgk_b[i];
            }
        }
    }
}

// ======== kernel 2: Q0 GEMM + wmu/wlv/wpq composites (Wq read once) ========
__global__ void k_q0(const float* __restrict__ feats, const float* __restrict__ Wq,
                     const float* __restrict__ bq,
                     const float* __restrict__ mu_w, const float* __restrict__ lv_w,
                     const float* __restrict__ pgq_w){
    __shared__ float sh[32][64];
    __shared__ float shw[64][64];
    int blk=blockIdx.x;
    int i=blk/144; int rem=blk%144; int et=rem/12; int kc=rem%12;
    int tx=threadIdx.x&63, ty=threadIdx.x>>6;
    int e=et*64+tx;
    int dbase=kc*64;
    for(int q=threadIdx.x;q<512;q+=256){
        int bb=q>>4, dd4=q&15;
        ((float4*)sh[bb])[dd4] =
            ((const float4*)(feats + (((size_t)i*Bb+bb)*Ss)*Dd + dbase))[dd4];
    }
    for(int q=threadIdx.x;q<1024;q+=256){
        int rr=q>>4, cc=q&15;
        ((float4*)shw[rr])[cc] =
            ((const float4*)(Wq + ((size_t)i*Dd + dbase+rr)*Dd + et*64))[cc];
    }
    __syncthreads();
    float acc[8];
    float binit=(kc==0)? bq[i*Dd+e] : 0.f;
    #pragma unroll
    for(int r=0;r<8;r++) acc[r]=binit;
    #pragma unroll 8
    for(int d=0;d<64;d++){
        float w=shw[d][tx];
        #pragma unroll
        for(int r=0;r<8;r++) acc[r]+=sh[ty+r*4][d]*w;
    }
    #pragma unroll
    for(int r=0;r<8;r++) atomicAdd(&g_Q0[i][ty+r*4][e], acc[r]);
    int wid=threadIdx.x>>5, lane=threadIdx.x&31;
    int ea=et*64+lane, eb=ea+32;
    float m0=mu_w[i*Dd+ea],  m1=mu_w[i*Dd+eb];
    float l0=lv_w[i*Dd+ea],  l1=lv_w[i*Dd+eb];
    float p0=pgq_w[i*Dd+ea], p1=pgq_w[i*Dd+eb];
    for(int rr=wid*8; rr<wid*8+8; rr++){
        float w0=shw[rr][lane], w1=shw[rr][lane+32];
        float a=w0*m0+w1*m1, b=w0*l0+w1*l1, c=w0*p0+w1*p1;
        a=warp_sum(a); b=warp_sum(b); c=warp_sum(c);
        if(!lane){
            atomicAdd(&g_wmu[i][dbase+rr],a);
            atomicAdd(&g_wlv[i][dbase+rr],b);
            atomicAdd(&g_wpq[i][dbase+rr],c);
        }
    }
}

// ======== kernel 3: qkvec GEMM + wpk composites (Wk read once) + qbk + pq0 ========
__global__ void k_qkvec(const float* __restrict__ Wk, const float* __restrict__ bk,
                        const float* __restrict__ pgk_w, const float* __restrict__ pgq_w,
                        const float* __restrict__ pgq_b){
    int blk=blockIdx.x;
    if(blk>=432){
        if(blk==438){
            // pq0[i][b] = Q0[i,b] . pgq_w[i] + pgq_b[i]   (96 dots)
            int wid=threadIdx.x>>5, lane=threadIdx.x&31;
            for(int t=wid;t<Mm*Bb;t+=8){
                int i=t/Bb, b=t%Bb;
                float a=0.f;
                for(int e=lane;e<Dd;e+=32) a += g_Q0[i][b][e]*pgq_w[i*Dd+e];
                a=warp_sum(a);
                if(!lane) g_pq0[i][b]=a+pgq_b[i];
            }
            return;
        }
        const int pi[6]={0,0,1,1,2,2}, pj[6]={1,2,0,2,0,1};
        int p=blk-432; int i=pi[p], j=pj[p];
        int wid=threadIdx.x>>5, lane=threadIdx.x&31;
        for(int b=wid;b<Bb;b+=8){
            float a=0.f;
            for(int e=lane;e<Dd;e+=32) a += bk[j*Dd+e]*g_Q0[i][b][e];
            a=warp_sum(a);
            if(!lane) g_qbk[i][j][b]=a;
        }
        return;
    }
    __shared__ float shq[64][64];
    __shared__ float shw[64][65];
    int j=blk/144; int rem=blk%144; int dt=rem/12; int kc=rem%12;
    int i0=(j==0)?1:0, i1=(j==2)?1:2;
    int tx=threadIdx.x&63, ty=threadIdx.x>>6;
    int d=dt*64+tx;
    int ebase=kc*64;
    for(int q=threadIdx.x;q<1024;q+=256){
        int rr=q>>4, cc=q&15;
        int ii=(rr<32)?i0:i1; int bb=rr&31;
        ((float4*)shq[rr])[cc] = ((const float4*)(&g_Q0[ii][bb][ebase]))[cc];
    }
    for(int q=threadIdx.x;q<1024;q+=256){
        int rr=q>>4, cc=q&15;
        float4 w4 = ((const float4*)(Wk + ((size_t)j*Dd + dt*64+rr)*Dd + ebase))[cc];
        shw[cc*4+0][rr]=w4.x; shw[cc*4+1][rr]=w4.y;
        shw[cc*4+2][rr]=w4.z; shw[cc*4+3][rr]=w4.w;
    }
    __syncthreads();
    float acc[16];
    #pragma unroll
    for(int r=0;r<16;r++) acc[r]=0.f;
    #pragma unroll 4
    for(int ee=0;ee<64;ee++){
        float w=shw[ee][tx];
        #pragma unroll
        for(int r=0;r<16;r++) acc[r]+=shq[ty+r*4][ee]*w;
    }
    #pragma unroll
    for(int r=0;r<16;r++){
        int vv=ty+r*4; int ii=(vv<32)?i0:i1; int bb=vv&31;
        atomicAdd(&g_qkvec[ii][j][bb][d], acc[r]);
    }
    int wid=threadIdx.x>>5, lane=threadIdx.x&31;
    float q00=pgk_w[0*Dd+ebase+lane], q01=pgk_w[0*Dd+ebase+lane+32];
    float q10=pgk_w[1*Dd+ebase+lane], q11=pgk_w[1*Dd+ebase+lane+32];
    float q20=pgk_w[2*Dd+ebase+lane], q21=pgk_w[2*Dd+ebase+lane+32];
    for(int rr=wid*8; rr<wid*8+8; rr++){
        float w0=shw[lane][rr], w1=shw[lane+32][rr];
        float a=w0*q00+w1*q01, b=w0*q10+w1*q11, c=w0*q20+w1*q21;
        a=warp_sum(a); b=warp_sum(b); c=warp_sum(c);
        if(!lane){
            atomicAdd(&g_wpk[0][j][dt*64+rr],a);
            atomicAdd(&g_wpk[1][j][dt*64+rr],b);
            atomicAdd(&g_wpk[2][j][dt*64+rr],c);
        }
    }
}

// ======== kernel 4: FUSED row stats + attention dots + kl (single feats pass) ========
// 768 blocks: (m, b, s-chunk of 32). 4 rows/warp, 6 dot-vectors (pqb dropped).
__global__ void __launch_bounds__(256, 3) k_rowstats(const float* __restrict__ feats){
    __shared__ float4 sw4[6][D4];
    __shared__ float skl[8];
    int blk=blockIdx.x;
    int m  = blk/256;
    int b  = (blk/8)%Bb;
    int sc = blk%8;
    int i0=(m==0)?1:0, i1=(m==2)?1:2;
    for(int d=threadIdx.x; d<D4; d+=256){
        sw4[0][d]=((const float4*)g_wmu[m])[d];
        sw4[1][d]=((const float4*)g_wlv[m])[d];
        sw4[2][d]=((const float4*)g_wpk[i0][m])[d];
        sw4[3][d]=((const float4*)g_wpk[i1][m])[d];
        sw4[4][d]=((const float4*)g_qkvec[i0][m][b])[d];
        sw4[5][d]=((const float4*)g_qkvec[i1][m][b])[d];
    }
    __syncthreads();
    int wid=threadIdx.x>>5, lane=threadIdx.x&31;
    const float* base = feats + ((size_t)m*Bb+b)*Ss*Dd;
    int s0 = sc*32 + wid*4;
    const float4* f0=(const float4*)(base + (size_t)s0*Dd);
    const float4* f1=f0+D4;
    const float4* f2=f1+D4;
    const float4* f3=f2+D4;
    float a[6][4];
    #pragma unroll
    for(int v=0;v<6;v++){
        a[v][0]=0.f; a[v][1]=0.f; a[v][2]=0.f; a[v][3]=0.f;
    }
    for(int d=lane; d<D4; d+=32){
        float4 x0=f0[d], x1=f1[d], x2=f2[d], x3=f3[d];
        #pragma unroll
        for(int v=0;v<6;v++){
            float4 w=sw4[v][d];
            a[v][0]+=dot4(x0,w);
            a[v][1]+=dot4(x1,w);
            a[v][2]+=dot4(x2,w);
            a[v][3]+=dot4(x3,w);
        }
    }
    #pragma unroll
    for(int v=0;v<6;v++){
        #pragma unroll
        for(int r=0;r<4;r++) a[v][r]=warp_sum(a[v][r]);
    }
    if(!lane){
        float qb0=g_qbk[i0][m][b], qb1=g_qbk[i1][m][b];
        float klacc=0.f;
        #pragma unroll
        for(int r=0;r<4;r++){
            int s = s0 + r;
            float mu=a[0][r]+g_cmu[m], lv=a[1][r]+g_clv[m];
            g_mu[m][b][s]=mu; g_lv[m][b][s]=lv;
            g_kd[i0][m][b][s]=a[2][r]+g_cpk[i0][m];
            g_kd[i1][m][b][s]=a[3][r]+g_cpk[i1][m];
            g_dotA[i0][m][b][s]=a[4][r]+qb0;
            g_dotA[i1][m][b][s]=a[5][r]+qb1;
            klacc += 1.f + lv - mu*mu - expf(lv);
        }
        skl[wid]=klacc;
    }
    __syncthreads();
    if(threadIdx.x==0){
        float t=0.f;
        #pragma unroll
        for(int w=0;w<8;w++) t+=skl[w];
        atomicAdd(&g_kl, t);
    }
}

// ======== kernel 5: gates + fused dual softmax + weighted feats sums (288 blocks) ========
__global__ void k_attn2(const float* __restrict__ feats, const float* __restrict__ eps,
                        const float* __restrict__ dyn){
    __shared__ float w0[Ss], w1[Ss];
    __shared__ float4 sr0[4][64], sr1[4][64];
    __shared__ float2 sred2[8];
    __shared__ float spq0, spq1;
    __shared__ float2 sscal2;
    int blk=blockIdx.x;
    int j  = blk/96;
    int b  = (blk/3)%Bb;
    int dc = blk%3;
    int i0=(j==0)?1:0, i1=(j==2)?1:2;
    int cnt0=(j<i0)? j : j-1;
    int cnt1=(j<i1)? j : j-1;
    int k=threadIdx.x;
    int wid=k>>5, lane=k&31;
    float dynv=dyn[0];
    float mu0=g_mu[i0][b][k], lv0=g_lv[i0][b][k];
    float e0 = eps[(((size_t)i0*(Mm-1)+cnt0)*Bb + b)*Ss + k];
    float gk0 = sigmoidf(mu0 + dynv*expf(0.5f*lv0)*e0);
    float pk0 = sigmoidf(g_kd[i0][j][b][k]) * gk0;
    float mu1=g_mu[i1][b][k], lv1=g_lv[i1][b][k];
    float e1 = eps[(((size_t)i1*(Mm-1)+cnt1)*Bb + b)*Ss + k];
    float gk1 = sigmoidf(mu1 + dynv*expf(0.5f*lv1)*e1);
    float pk1 = sigmoidf(g_kd[i1][j][b][k]) * gk1;
    if(k==0){
        spq0 = sigmoidf(g_pq0[i0][b]) * gk0;
        spq1 = sigmoidf(g_pq0[i1][b]) * gk1;
    }
    __syncthreads();
    float l0 = g_dotA[i0][j][b][k]*SCALE*spq0*pk0;
    float l1 = g_dotA[i1][j][b][k]*SCALE*spq1*pk1;
    // fused dual max-reduction
    {
        float mx0=l0, mx1=l1;
        #pragma unroll
        for(int o=16;o>0;o>>=1){
            mx0=fmaxf(mx0,__shfl_xor_sync(0xffffffffu,mx0,o));
            mx1=fmaxf(mx1,__shfl_xor_sync(0xffffffffu,mx1,o));
        }
        if(!lane) sred2[wid]=make_float2(mx0,mx1);
        __syncthreads();
        if(threadIdx.x==0){
            float t0=sred2[0].x, t1=sred2[0].y;
            #pragma unroll
            for(int w=1;w<8;w++){ t0=fmaxf(t0,sred2[w].x); t1=fmaxf(t1,sred2[w].y); }
            sscal2=make_float2(t0,t1);
        }
        __syncthreads();
    }
    float ex0=expf(l0-sscal2.x), ex1=expf(l1-sscal2.y);
    // fused dual sum-reduction
    {
        float sm0=ex0, sm1=ex1;
        #pragma unroll
        for(int o=16;o>0;o>>=1){
            sm0+=__shfl_xor_sync(0xffffffffu,sm0,o);
            sm1+=__shfl_xor_sync(0xffffffffu,sm1,o);
        }
        if(!lane) sred2[wid]=make_float2(sm0,sm1);
        __syncthreads();
        if(threadIdx.x==0){
            float t0=0.f, t1=0.f;
            #pragma unroll
            for(int w=0;w<8;w++){ t0+=sred2[w].x; t1+=sred2[w].y; }
            sscal2=make_float2(t0,t1);
        }
        __syncthreads();
    }
    w0[k]=ex0/sscal2.x;
    w1[k]=ex1/sscal2.y;
    __syncthreads();
    // weighted sum: thread=(kq,d4); float4 over 64-k chunk
    int d4 = threadIdx.x&63, kq = threadIdx.x>>6;
    const float4* f4 = (const float4*)(feats + (((size_t)j*Bb+b)*Ss)*Dd);
    int col = dc*64 + d4;
    float4 a0=make_float4(0.f,0.f,0.f,0.f), a1=a0;
    int kst=kq*64;
    #pragma unroll 8
    for(int kk=kst;kk<kst+64;kk++){
        float4 f = f4[(size_t)kk*D4 + col];
        float x0=w0[kk], x1=w1[kk];
        a0.x+=x0*f.x; a0.y+=x0*f.y; a0.z+=x0*f.z; a0.w+=x0*f.w;
        a1.x+=x1*f.x; a1.y+=x1*f.y; a1.z+=x1*f.z; a1.w+=x1*f.w;
    }
    sr0[kq][d4]=a0; sr1[kq][d4]=a1;
    __syncthreads();
    if(threadIdx.x<64){
        int d=threadIdx.x;
        float4 t0=sr0[0][d], t1=sr0[1][d], t2=sr0[2][d], t3=sr0[3][d];
        float4 u0=sr1[0][d], u1=sr1[1][d], u2=sr1[2][d], u3=sr1[3][d];
        float4 s0=make_float4(t0.x+t1.x+t2.x+t3.x, t0.y+t1.y+t2.y+t3.y,
                              t0.z+t1.z+t2.z+t3.z, t0.w+t1.w+t2.w+t3.w);
        float4 s1=make_float4(u0.x+u1.x+u2.x+u3.x, u0.y+u1.y+u2.y+u3.y,
                              u0.z+u1.z+u2.z+u3.z, u0.w+u1.w+u2.w+u3.w);
        ((float4*)&g_wf[i0][j][b][dc*256])[d] = s0;
        ((float4*)&g_wf[i1][j][b][dc*256])[d] = s1;
    }
}

// ======== kernel 6: agg += wf @ Wv (864 single-tile blocks) ========
__global__ void k_agg(const float* __restrict__ Wv, const float* __restrict__ bv){
    __shared__ float sh[32][64];
    __shared__ float shw[64][64];
    int blk=blockIdx.x;
    int i = blk/288; int rem=blk%288;
    int et = rem/24; int rem2=rem%24;
    int jj = rem2/12; int kc = rem2%12;
    int j0=(i==0)?1:0, j1=(i==2)?1:2;
    int j = jj? j1 : j0;
    int tx=threadIdx.x&63, ty=threadIdx.x>>6;
    int e=et*64+tx;
    int dbase=kc*64;
    for(int q=threadIdx.x;q<512;q+=256){
        int bb=q>>4, dd4=q&15;
        ((float4*)sh[bb])[dd4] = ((const float4*)(&g_wf[i][j][bb][dbase]))[dd4];
    }
    for(int q=threadIdx.x;q<1024;q+=256){
        int rr=q>>4, cc=q&15;
        ((float4*)shw[rr])[cc] =
            ((const float4*)(Wv + ((size_t)j*Dd + dbase+rr)*Dd + et*64))[cc];
    }
    __syncthreads();
    float acc[8];
    float binit = (kc==0)? bv[j*Dd+e] : 0.f;
    #pragma unroll
    for(int r=0;r<8;r++) acc[r]=binit;
    #pragma unroll 8
    for(int d=0;d<64;d++){
        float w=shw[d][tx];
        #pragma unroll
        for(int r=0;r<8;r++) acc[r]+=sh[ty+r*4][d]*w;
    }
    #pragma unroll
    for(int r=0;r<8;r++) atomicAdd(&g_agg[i][ty+r*4][e], acc[r]);
}

// ======== kernel 7: E/G accumulation (1296 single-tile blocks) ========
__global__ void k_eg(const float* __restrict__ WE, const float* __restrict__ WEb,
                     const float* __restrict__ Wh, const float* __restrict__ Whb,
                     const float* __restrict__ Wqc, const float* __restrict__ Wqcb){
    __shared__ float sh[32][64];
    __shared__ float shw[64][64];
    int blk=blockIdx.x;
    int i = blk/432; int rem=blk%432;
    int et = rem/36; int rem2=rem%36;
    int seg = rem2/12; int kc = rem2%12;
    int tx=threadIdx.x&63, ty=threadIdx.x>>6;
    int e=et*64+tx;
    int dbase=kc*64;
    const float* W  = (seg==0)? WE : (seg==1)? Wh : Wqc;
    const float* src = (seg==2)? &g_Q0[i][0][0] : &g_agg[i][0][0];
    float* dst = (seg==0)? &g_E[i][0][0] : &g_G[i][0][0];
    for(int q=threadIdx.x;q<512;q+=256){
        int bb=q>>4, dd4=q&15;
        ((float4*)sh[bb])[dd4] = ((const float4*)(src + (size_t)bb*Dd + dbase))[dd4];
    }
    for(int q=threadIdx.x;q<1024;q+=256){
        int rr=q>>4, cc=q&15;
        ((float4*)shw[rr])[cc] =
            ((const float4*)(W + ((size_t)i*Dd + dbase+rr)*Dd + et*64))[cc];
    }
    __syncthreads();
    float binit = 0.f;
    if(kc==0){
        if(seg==0) binit = WEb[i*Dd+e];
        else if(seg==1) binit = Whb[i*Dd+e]+Wqcb[i*Dd+e];
    }
    float acc[8];
    #pragma unroll
    for(int r=0;r<8;r++) acc[r]=binit;
    #pragma unroll 8
    for(int d=0;d<64;d++){
        float w=shw[d][tx];
        #pragma unroll
        for(int r=0;r<8;r++) acc[r]+=sh[ty+r*4][d]*w;
    }
    #pragma unroll
    for(int r=0;r<8;r++) atomicAdd(dst + (size_t)(ty+r*4)*Dd + e, acc[r]);
}

__device__ __forceinline__ float block_sum256(float v, float* sred){
    v = warp_sum(v);
    int wid=threadIdx.x>>5, lane=threadIdx.x&31;
    if(!lane) sred[wid]=v;
    __syncthreads();
    float t = (threadIdx.x<8)? sred[threadIdx.x] : 0.f;
    if(threadIdx.x<32){
        #pragma unroll
        for(int o=16;o>0;o>>=1) t += __shfl_xor_sync(0xffffffffu,t,o);
        if(threadIdx.x==0) sred[0]=t;
    }
    __syncthreads();
    float r = sred[0];
    __syncthreads();
    return r;
}

// ======== kernel 8: C = LN(relu(E))*LN(relu(G))  +  dout bias init ========
__global__ void k_lnprod(const float* __restrict__ lnEg, const float* __restrict__ lnEb,
                         const float* __restrict__ lnGg, const float* __restrict__ lnGb,
                         const float* __restrict__ out_b, float* __restrict__ dout){
    if(blockIdx.x >= Mm*Bb){
        int b = blockIdx.x - Mm*Bb;
        #pragma unroll
        for(int t=0;t<4;t++)
            dout[(size_t)b*Hh + t*256 + threadIdx.x] = out_b[t*256 + threadIdx.x];
        return;
    }
    __shared__ float sred[8];
    int i = blockIdx.x/Bb, b = blockIdx.x%Bb;
    float se=0.f, se2=0.f, sg=0.f, sg2=0.f;
    for(int d=threadIdx.x; d<Dd; d+=256){
        float ev=fmaxf(g_E[i][b][d],0.f), gv=fmaxf(g_G[i][b][d],0.f);
        se+=ev; se2+=ev*ev; sg+=gv; sg2+=gv*gv;
    }
    se  = block_sum256(se , sred);
    se2 = block_sum256(se2, sred);
    sg  = block_sum256(sg , sred);
    sg2 = block_sum256(sg2, sred);
    float mE = se/(float)Dd,  vE = se2/(float)Dd - mE*mE;
    float mG = sg/(float)Dd,  vG = sg2/(float)Dd - mG*mG;
    float rE = rsqrtf(vE + LNEPS), rG = rsqrtf(vG + LNEPS);
    for(int d=threadIdx.x; d<Dd; d+=256){
        float nE = (fmaxf(g_E[i][b][d],0.f)-mE)*rE*lnEg[i*Dd+d] + lnEb[i*Dd+d];
        float nG = (fmaxf(g_G[i][b][d],0.f)-mG)*rG*lnGg[i*Dd+d] + lnGb[i*Dd+d];
        g_C[i][b][d] = nE*nG;
    }
}

// ======== kernel 9: out += fused @ out_w (576 single-tile blocks) + kl ========
__global__ void k_out(const float* __restrict__ out_w, float* __restrict__ dout,
                      int write_kl){
    int blk=blockIdx.x;
    if(blk>=576){
        if(threadIdx.x==0 && write_kl) dout[Bb*Hh] = -0.5f*(float)(Mm-1)*g_kl;
        return;
    }
    __shared__ float sf[32][64];
    __shared__ float shw[64][64];
    int ht = blk/36;
    int kc = blk%36;
    int c0 = kc*64;
    int ii = c0/Dd; int dd = c0%Dd;
    int tx=threadIdx.x&63, ty=threadIdx.x>>6;
    int h = ht*64 + tx;
    for(int q=threadIdx.x;q<512;q+=256){
        int bb=q>>4, dd4=q&15;
        ((float4*)sf[bb])[dd4] = ((const float4*)(&g_C[ii][bb][dd]))[dd4];
    }
    for(int q=threadIdx.x;q<1024;q+=256){
        int rr=q>>4, cc=q&15;
        ((float4*)shw[rr])[cc] =
            ((const float4*)(out_w + ((size_t)(c0+rr))*Hh + ht*64))[cc];
    }
    __syncthreads();
    float acc[8];
    #pragma unroll
    for(int r=0;r<8;r++) acc[r]=0.f;
    #pragma unroll 8
    for(int d=0;d<64;d++){
        float w=shw[d][tx];
        #pragma unroll
        for(int r=0;r<8;r++) acc[r]+=sf[ty+r*4][d]*w;
    }
    #pragma unroll
    for(int r=0;r<8;r++) atomicAdd(&dout[(size_t)(ty+r*4)*Hh + h], acc[r]);
}

extern "C" void kernel_launch(void* const* d_in, const int* in_sizes, int n_in,
                              void* d_out, int out_size) {
    const float* feats = (const float*)d_in[0];
    const float* Wq    = (const float*)d_in[1];
    const float* bq    = (const float*)d_in[2];
    const float* Wk    = (const float*)d_in[3];
    const float* bk    = (const float*)d_in[4];
    const float* Wv    = (const float*)d_in[5];
    const float* bv    = (const float*)d_in[6];
    const float* pgq_w = (const float*)d_in[7];
    const float* pgq_b = (const float*)d_in[8];
    const float* pgk_w = (const float*)d_in[9];
    const float* pgk_b = (const float*)d_in[10];
    const float* mu_w  = (const float*)d_in[11];
    const float* mu_b  = (const float*)d_in[12];
    const float* lv_w  = (const float*)d_in[13];
    const float* lv_b  = (const float*)d_in[14];
    const float* dyn   = (const float*)d_in[15];
    const float* WE_w  = (const float*)d_in[16];
    const float* WE_b  = (const float*)d_in[17];
    const float* Wh_w  = (const float*)d_in[18];
    const float* Wh_b  = (const float*)d_in[19];
    const float* Wqc_w = (const float*)d_in[20];
    const float* Wqc_b = (const float*)d_in[21];
    const float* lnE_g = (const float*)d_in[22];
    const float* lnE_b = (const float*)d_in[23];
    const float* lnG_g = (const float*)d_in[24];
    const float* lnG_b = (const float*)d_in[25];
    const float* out_w = (const float*)d_in[26];
    const float* out_b = (const float*)d_in[27];
    const float* eps   = (const float*)d_in[28];
    float* dout = (float*)d_out;

    k_init<<<161,256>>>(bq, bk, mu_w, mu_b, lv_w, lv_b, pgq_w, pgq_b, pgk_w, pgk_b);
    k_q0<<<432,256>>>(feats, Wq, bq, mu_w, lv_w, pgq_w);
    k_qkvec<<<439,256>>>(Wk, bk, pgk_w, pgq_w, pgq_b);
    k_rowstats<<<768,256>>>(feats);
    k_attn2<<<288,256>>>(feats, eps, dyn);
    k_agg<<<864,256>>>(Wv, bv);
    k_eg<<<1296,256>>>(WE_w, WE_b, Wh_w, Wh_b, Wqc_w, Wqc_b);
    k_lnprod<<<128,256>>>(lnE_g, lnE_b, lnG_g, lnG_b, out_b, dout);
    k_out<<<577,256>>>(out_w, dout, (out_size > Bb*Hh) ? 1 : 0);
}

// round 12
// speedup vs baseline: 1.0166x; 1.0166x over previous
#include <cuda_runtime.h>
#include <math.h>

#define Mm 3
#define Bb 32
#define Ss 256
#define Dd 768
#define D4 192
#define Hh 1024
#define NPAIR 6
#define LNEPS 1e-5f
#define SCALE 0.036084391824351615f

// ---------------- scratch (__device__ globals) ------------
__device__ __align__(16) float g_wmu[Mm][Dd], g_wlv[Mm][Dd], g_wpq[Mm][Dd]; // atomic accum
__device__ float g_cmu[Mm], g_clv[Mm];
__device__ __align__(16) float g_wpk[Mm][Mm][Dd];                            // atomic accum
__device__ float g_cpk[Mm][Mm];
__device__ __align__(16) float g_Q0[Mm][Bb][Dd];          // atomic accum
__device__ __align__(16) float g_qkvec[Mm][Mm][Bb][Dd];   // atomic accum
__device__ float g_qbk[Mm][Mm][Bb];
__device__ float g_pq0[Mm][Bb];                            // pq logit at s=0
__device__ float g_mu[Mm][Bb][Ss], g_lv[Mm][Bb][Ss];
__device__ float g_kd[Mm][Mm][Bb][Ss];
__device__ float g_dotA[Mm][Mm][Bb][Ss];
__device__ __align__(16) float g_wf[Mm][Mm][Bb][Dd];
__device__ __align__(16) float g_agg[Mm][Bb][Dd];         // atomic accum
__device__ __align__(16) float g_E[Mm][Bb][Dd], g_G[Mm][Bb][Dd]; // atomic accum
__device__ __align__(16) float g_C[Mm][Bb][Dd];
__device__ float g_kl;

__device__ __forceinline__ float warp_sum(float v){
    #pragma unroll
    for(int o=16;o>0;o>>=1) v += __shfl_down_sync(0xffffffffu, v, o);
    return v;
}
__device__ __forceinline__ float sigmoidf(float x){ return 1.f/(1.f+expf(-x)); }
__device__ __forceinline__ float dot4(float4 a, float4 b){
    return a.x*b.x + a.y*b.y + a.z*b.z + a.w*b.w;
}

// ======== kernel 1: zero accumulators + scalar constants ========
__global__ void k_init(const float* __restrict__ bq, const float* __restrict__ bk,
                       const float* __restrict__ mu_w, const float* __restrict__ mu_b,
                       const float* __restrict__ lv_w, const float* __restrict__ lv_b,
                       const float* __restrict__ pgq_w, const float* __restrict__ pgq_b,
                       const float* __restrict__ pgk_w, const float* __restrict__ pgk_b){
    if(blockIdx.x < 160){
        int tid = blockIdx.x*256 + threadIdx.x;
        const int stride = 160*256;
        float* p;
        p=&g_Q0[0][0][0];       for(int i=tid;i<Mm*Bb*Dd;i+=stride)    p[i]=0.f;
        p=&g_qkvec[0][0][0][0]; for(int i=tid;i<Mm*Mm*Bb*Dd;i+=stride) p[i]=0.f;
        p=&g_agg[0][0][0];      for(int i=tid;i<Mm*Bb*Dd;i+=stride)    p[i]=0.f;
        p=&g_E[0][0][0];        for(int i=tid;i<Mm*Bb*Dd;i+=stride)    p[i]=0.f;
        p=&g_G[0][0][0];        for(int i=tid;i<Mm*Bb*Dd;i+=stride)    p[i]=0.f;
        p=&g_wmu[0][0];         for(int i=tid;i<Mm*Dd;i+=stride)       p[i]=0.f;
        p=&g_wlv[0][0];         for(int i=tid;i<Mm*Dd;i+=stride)       p[i]=0.f;
        p=&g_wpq[0][0];         for(int i=tid;i<Mm*Dd;i+=stride)       p[i]=0.f;
        p=&g_wpk[0][0][0];      for(int i=tid;i<Mm*Mm*Dd;i+=stride)    p[i]=0.f;
        if(tid==0) g_kl=0.f;
    } else {
        int wid=threadIdx.x>>5, lane=threadIdx.x&31;
        for(int t=wid;t<15;t+=8){
            if(t<6){
                int m=t/2, which=t%2;
                const float* wv = (which==0)? mu_w : lv_w;
                float a=0.f;
                for(int e=lane;e<Dd;e+=32) a += bq[m*Dd+e]*wv[m*Dd+e];
                a=warp_sum(a);
                if(!lane){
                    if(which==0) g_cmu[m]=a+mu_b[m];
                    else g_clv[m]=a+lv_b[m];
                }
            } else {
                int q=t-6; int i=q/3, j=q%3;
                float a=0.f;
                for(int e=lane;e<Dd;e+=32) a += bk[j*Dd+e]*pgk_w[i*Dd+e];
                a=warp_sum(a);
                if(!lane) g_cpk[i][j]=a+pgk_b[i];
            }
        }
    }
}

// ======== kernel 2: Q0 GEMM + wmu/wlv/wpq composites (Wq read once) ========
__global__ void k_q0(const float* __restrict__ feats, const float* __restrict__ Wq,
                     const float* __restrict__ bq,
                     const float* __restrict__ mu_w, const float* __restrict__ lv_w,
                     const float* __restrict__ pgq_w){
    __shared__ float sh[32][64];
    __shared__ float shw[64][64];
    int blk=blockIdx.x;
    int i=blk/144; int rem=blk%144; int et=rem/12; int kc=rem%12;
    int tx=threadIdx.x&63, ty=threadIdx.x>>6;
    int e=et*64+tx;
    int dbase=kc*64;
    for(int q=threadIdx.x;q<512;q+=256){
        int bb=q>>4, dd4=q&15;
        ((float4*)sh[bb])[dd4] =
            ((const float4*)(feats + (((size_t)i*Bb+bb)*Ss)*Dd + dbase))[dd4];
    }
    for(int q=threadIdx.x;q<1024;q+=256){
        int rr=q>>4, cc=q&15;
        ((float4*)shw[rr])[cc] =
            ((const float4*)(Wq + ((size_t)i*Dd + dbase+rr)*Dd + et*64))[cc];
    }
    __syncthreads();
    float acc[8];
    float binit=(kc==0)? bq[i*Dd+e] : 0.f;
    #pragma unroll
    for(int r=0;r<8;r++) acc[r]=binit;
    #pragma unroll 8
    for(int d=0;d<64;d++){
        float w=shw[d][tx];
        #pragma unroll
        for(int r=0;r<8;r++) acc[r]+=sh[ty+r*4][d]*w;
    }
    #pragma unroll
    for(int r=0;r<8;r++) atomicAdd(&g_Q0[i][ty+r*4][e], acc[r]);
    int wid=threadIdx.x>>5, lane=threadIdx.x&31;
    int ea=et*64+lane, eb=ea+32;
    float m0=mu_w[i*Dd+ea],  m1=mu_w[i*Dd+eb];
    float l0=lv_w[i*Dd+ea],  l1=lv_w[i*Dd+eb];
    float p0=pgq_w[i*Dd+ea], p1=pgq_w[i*Dd+eb];
    for(int rr=wid*8; rr<wid*8+8; rr++){
        float w0=shw[rr][lane], w1=shw[rr][lane+32];
        float a=w0*m0+w1*m1, b=w0*l0+w1*l1, c=w0*p0+w1*p1;
        a=warp_sum(a); b=warp_sum(b); c=warp_sum(c);
        if(!lane){
            atomicAdd(&g_wmu[i][dbase+rr],a);
            atomicAdd(&g_wlv[i][dbase+rr],b);
            atomicAdd(&g_wpq[i][dbase+rr],c);
        }
    }
}

// ======== kernel 3: qkvec GEMM + wpk composites (Wk read once) + qbk + pq0 ========
__global__ void k_qkvec(const float* __restrict__ Wk, const float* __restrict__ bk,
                        const float* __restrict__ pgk_w, const float* __restrict__ pgq_w,
                        const float* __restrict__ pgq_b){
    int blk=blockIdx.x;
    if(blk>=432){
        if(blk==438){
            // pq0[i][b] = Q0[i,b] . pgq_w[i] + pgq_b[i]   (96 dots)
            int wid=threadIdx.x>>5, lane=threadIdx.x&31;
            for(int t=wid;t<Mm*Bb;t+=8){
                int i=t/Bb, b=t%Bb;
                float a=0.f;
                for(int e=lane;e<Dd;e+=32) a += g_Q0[i][b][e]*pgq_w[i*Dd+e];
                a=warp_sum(a);
                if(!lane) g_pq0[i][b]=a+pgq_b[i];
            }
            return;
        }
        const int pi[6]={0,0,1,1,2,2}, pj[6]={1,2,0,2,0,1};
        int p=blk-432; int i=pi[p], j=pj[p];
        int wid=threadIdx.x>>5, lane=threadIdx.x&31;
        for(int b=wid;b<Bb;b+=8){
            float a=0.f;
            for(int e=lane;e<Dd;e+=32) a += bk[j*Dd+e]*g_Q0[i][b][e];
            a=warp_sum(a);
            if(!lane) g_qbk[i][j][b]=a;
        }
        return;
    }
    __shared__ float shq[64][64];
    __shared__ float shw[64][65];
    int j=blk/144; int rem=blk%144; int dt=rem/12; int kc=rem%12;
    int i0=(j==0)?1:0, i1=(j==2)?1:2;
    int tx=threadIdx.x&63, ty=threadIdx.x>>6;
    int d=dt*64+tx;
    int ebase=kc*64;
    for(int q=threadIdx.x;q<1024;q+=256){
        int rr=q>>4, cc=q&15;
        int ii=(rr<32)?i0:i1; int bb=rr&31;
        ((float4*)shq[rr])[cc] = ((const float4*)(&g_Q0[ii][bb][ebase]))[cc];
    }
    for(int q=threadIdx.x;q<1024;q+=256){
        int rr=q>>4, cc=q&15;
        float4 w4 = ((const float4*)(Wk + ((size_t)j*Dd + dt*64+rr)*Dd + ebase))[cc];
        shw[cc*4+0][rr]=w4.x; shw[cc*4+1][rr]=w4.y;
        shw[cc*4+2][rr]=w4.z; shw[cc*4+3][rr]=w4.w;
    }
    __syncthreads();
    float acc[16];
    #pragma unroll
    for(int r=0;r<16;r++) acc[r]=0.f;
    #pragma unroll 4
    for(int ee=0;ee<64;ee++){
        float w=shw[ee][tx];
        #pragma unroll
        for(int r=0;r<16;r++) acc[r]+=shq[ty+r*4][ee]*w;
    }
    #pragma unroll
    for(int r=0;r<16;r++){
        int vv=ty+r*4; int ii=(vv<32)?i0:i1; int bb=vv&31;
        atomicAdd(&g_qkvec[ii][j][bb][d], acc[r]);
    }
    int wid=threadIdx.x>>5, lane=threadIdx.x&31;
    float q00=pgk_w[0*Dd+ebase+lane], q01=pgk_w[0*Dd+ebase+lane+32];
    float q10=pgk_w[1*Dd+ebase+lane], q11=pgk_w[1*Dd+ebase+lane+32];
    float q20=pgk_w[2*Dd+ebase+lane], q21=pgk_w[2*Dd+ebase+lane+32];
    for(int rr=wid*8; rr<wid*8+8; rr++){
        float w0=shw[lane][rr], w1=shw[lane+32][rr];
        float a=w0*q00+w1*q01, b=w0*q10+w1*q11, c=w0*q20+w1*q21;
        a=warp_sum(a); b=warp_sum(b); c=warp_sum(c);
        if(!lane){
            atomicAdd(&g_wpk[0][j][dt*64+rr],a);
            atomicAdd(&g_wpk[1][j][dt*64+rr],b);
            atomicAdd(&g_wpk[2][j][dt*64+rr],c);
        }
    }
}

// ======== kernel 4: FUSED row stats + attention dots + kl (single feats pass) ========
// 768 blocks: (m, b, s-chunk of 32). 4 rows/warp, 6 dot-vectors (pqb dropped).
__global__ void __launch_bounds__(256, 3) k_rowstats(const float* __restrict__ feats){
    __shared__ float4 sw4[6][D4];
    __shared__ float skl[8];
    int blk=blockIdx.x;
    int m  = blk/256;
    int b  = (blk/8)%Bb;
    int sc = blk%8;
    int i0=(m==0)?1:0, i1=(m==2)?1:2;
    for(int d=threadIdx.x; d<D4; d+=256){
        sw4[0][d]=((const float4*)g_wmu[m])[d];
        sw4[1][d]=((const float4*)g_wlv[m])[d];
        sw4[2][d]=((const float4*)g_wpk[i0][m])[d];
        sw4[3][d]=((const float4*)g_wpk[i1][m])[d];
        sw4[4][d]=((const float4*)g_qkvec[i0][m][b])[d];
        sw4[5][d]=((const float4*)g_qkvec[i1][m][b])[d];
    }
    __syncthreads();
    int wid=threadIdx.x>>5, lane=threadIdx.x&31;
    const float* base = feats + ((size_t)m*Bb+b)*Ss*Dd;
    int s0 = sc*32 + wid*4;
    const float4* f0=(const float4*)(base + (size_t)s0*Dd);
    const float4* f1=f0+D4;
    const float4* f2=f1+D4;
    const float4* f3=f2+D4;
    float a[6][4];
    #pragma unroll
    for(int v=0;v<6;v++){
        a[v][0]=0.f; a[v][1]=0.f; a[v][2]=0.f; a[v][3]=0.f;
    }
    for(int d=lane; d<D4; d+=32){
        float4 x0=f0[d], x1=f1[d], x2=f2[d], x3=f3[d];
        #pragma unroll
        for(int v=0;v<6;v++){
            float4 w=sw4[v][d];
            a[v][0]+=dot4(x0,w);
            a[v][1]+=dot4(x1,w);
            a[v][2]+=dot4(x2,w);
            a[v][3]+=dot4(x3,w);
        }
    }
    #pragma unroll
    for(int v=0;v<6;v++){
        #pragma unroll
        for(int r=0;r<4;r++) a[v][r]=warp_sum(a[v][r]);
    }
    if(!lane){
        float qb0=g_qbk[i0][m][b], qb1=g_qbk[i1][m][b];
        float klacc=0.f;
        #pragma unroll
        for(int r=0;r<4;r++){
            int s = s0 + r;
            float mu=a[0][r]+g_cmu[m], lv=a[1][r]+g_clv[m];
            g_mu[m][b][s]=mu; g_lv[m][b][s]=lv;
            g_kd[i0][m][b][s]=a[2][r]+g_cpk[i0][m];
            g_kd[i1][m][b][s]=a[3][r]+g_cpk[i1][m];
            g_dotA[i0][m][b][s]=a[4][r]+qb0;
            g_dotA[i1][m][b][s]=a[5][r]+qb1;
            klacc += 1.f + lv - mu*mu - expf(lv);
        }
        skl[wid]=klacc;
    }
    __syncthreads();
    if(threadIdx.x==0){
        float t=0.f;
        #pragma unroll
        for(int w=0;w<8;w++) t+=skl[w];
        atomicAdd(&g_kl, t);
    }
}

// ======== kernel 5: gates + fused dual softmax + weighted feats sums (288 blocks) ========
__global__ void k_attn2(const float* __restrict__ feats, const float* __restrict__ eps,
                        const float* __restrict__ dyn){
    __shared__ float w0[Ss], w1[Ss];
    __shared__ float4 sr0[4][64], sr1[4][64];
    __shared__ float2 sred2[8];
    __shared__ float spq0, spq1;
    __shared__ float2 sscal2;
    int blk=blockIdx.x;
    int j  = blk/96;
    int b  = (blk/3)%Bb;
    int dc = blk%3;
    int i0=(j==0)?1:0, i1=(j==2)?1:2;
    int cnt0=(j<i0)? j : j-1;
    int cnt1=(j<i1)? j : j-1;
    int k=threadIdx.x;
    int wid=k>>5, lane=k&31;
    float dynv=dyn[0];
    float mu0=g_mu[i0][b][k], lv0=g_lv[i0][b][k];
    float e0 = eps[(((size_t)i0*(Mm-1)+cnt0)*Bb + b)*Ss + k];
    float gk0 = sigmoidf(mu0 + dynv*expf(0.5f*lv0)*e0);
    float pk0 = sigmoidf(g_kd[i0][j][b][k]) * gk0;
    float mu1=g_mu[i1][b][k], lv1=g_lv[i1][b][k];
    float e1 = eps[(((size_t)i1*(Mm-1)+cnt1)*Bb + b)*Ss + k];
    float gk1 = sigmoidf(mu1 + dynv*expf(0.5f*lv1)*e1);
    float pk1 = sigmoidf(g_kd[i1][j][b][k]) * gk1;
    if(k==0){
        spq0 = sigmoidf(g_pq0[i0][b]) * gk0;
        spq1 = sigmoidf(g_pq0[i1][b]) * gk1;
    }
    __syncthreads();
    float l0 = g_dotA[i0][j][b][k]*SCALE*spq0*pk0;
    float l1 = g_dotA[i1][j][b][k]*SCALE*spq1*pk1;
    // fused dual max-reduction
    {
        float mx0=l0, mx1=l1;
        #pragma unroll
        for(int o=16;o>0;o>>=1){
            mx0=fmaxf(mx0,__shfl_xor_sync(0xffffffffu,mx0,o));
            mx1=fmaxf(mx1,__shfl_xor_sync(0xffffffffu,mx1,o));
        }
        if(!lane) sred2[wid]=make_float2(mx0,mx1);
        __syncthreads();
        if(threadIdx.x==0){
            float t0=sred2[0].x, t1=sred2[0].y;
            #pragma unroll
            for(int w=1;w<8;w++){ t0=fmaxf(t0,sred2[w].x); t1=fmaxf(t1,sred2[w].y); }
            sscal2=make_float2(t0,t1);
        }
        __syncthreads();
    }
    float ex0=expf(l0-sscal2.x), ex1=expf(l1-sscal2.y);
    // fused dual sum-reduction
    {
        float sm0=ex0, sm1=ex1;
        #pragma unroll
        for(int o=16;o>0;o>>=1){
            sm0+=__shfl_xor_sync(0xffffffffu,sm0,o);
            sm1+=__shfl_xor_sync(0xffffffffu,sm1,o);
        }
        if(!lane) sred2[wid]=make_float2(sm0,sm1);
        __syncthreads();
        if(threadIdx.x==0){
            float t0=0.f, t1=0.f;
            #pragma unroll
            for(int w=0;w<8;w++){ t0+=sred2[w].x; t1+=sred2[w].y; }
            sscal2=make_float2(t0,t1);
        }
        __syncthreads();
    }
    w0[k]=ex0/sscal2.x;
    w1[k]=ex1/sscal2.y;
    __syncthreads();
    // weighted sum: thread=(kq,d4); float4 over 64-k chunk
    int d4 = threadIdx.x&63, kq = threadIdx.x>>6;
    const float4* f4 = (const float4*)(feats + (((size_t)j*Bb+b)*Ss)*Dd);
    int col = dc*64 + d4;
    float4 a0=make_float4(0.f,0.f,0.f,0.f), a1=a0;
    int kst=kq*64;
    #pragma unroll 8
    for(int kk=kst;kk<kst+64;kk++){
        float4 f = f4[(size_t)kk*D4 + col];
        float x0=w0[kk], x1=w1[kk];
        a0.x+=x0*f.x; a0.y+=x0*f.y; a0.z+=x0*f.z; a0.w+=x0*f.w;
        a1.x+=x1*f.x; a1.y+=x1*f.y; a1.z+=x1*f.z; a1.w+=x1*f.w;
    }
    sr0[kq][d4]=a0; sr1[kq][d4]=a1;
    __syncthreads();
    if(threadIdx.x<64){
        int d=threadIdx.x;
        float4 t0=sr0[0][d], t1=sr0[1][d], t2=sr0[2][d], t3=sr0[3][d];
        float4 u0=sr1[0][d], u1=sr1[1][d], u2=sr1[2][d], u3=sr1[3][d];
        float4 s0=make_float4(t0.x+t1.x+t2.x+t3.x, t0.y+t1.y+t2.y+t3.y,
                              t0.z+t1.z+t2.z+t3.z, t0.w+t1.w+t2.w+t3.w);
        float4 s1=make_float4(u0.x+u1.x+u2.x+u3.x, u0.y+u1.y+u2.y+u3.y,
                              u0.z+u1.z+u2.z+u3.z, u0.w+u1.w+u2.w+u3.w);
        ((float4*)&g_wf[i0][j][b][dc*256])[d] = s0;
        ((float4*)&g_wf[i1][j][b][dc*256])[d] = s1;
    }
}

// ======== kernel 6: agg += wf @ Wv (864 single-tile blocks) ========
__global__ void k_agg(const float* __restrict__ Wv, const float* __restrict__ bv){
    __shared__ float sh[32][64];
    __shared__ float shw[64][64];
    int blk=blockIdx.x;
    int i = blk/288; int rem=blk%288;
    int et = rem/24; int rem2=rem%24;
    int jj = rem2/12; int kc = rem2%12;
    int j0=(i==0)?1:0, j1=(i==2)?1:2;
    int j = jj? j1 : j0;
    int tx=threadIdx.x&63, ty=threadIdx.x>>6;
    int e=et*64+tx;
    int dbase=kc*64;
    for(int q=threadIdx.x;q<512;q+=256){
        int bb=q>>4, dd4=q&15;
        ((float4*)sh[bb])[dd4] = ((const float4*)(&g_wf[i][j][bb][dbase]))[dd4];
    }
    for(int q=threadIdx.x;q<1024;q+=256){
        int rr=q>>4, cc=q&15;
        ((float4*)shw[rr])[cc] =
            ((const float4*)(Wv + ((size_t)j*Dd + dbase+rr)*Dd + et*64))[cc];
    }
    __syncthreads();
    float acc[8];
    float binit = (kc==0)? bv[j*Dd+e] : 0.f;
    #pragma unroll
    for(int r=0;r<8;r++) acc[r]=binit;
    #pragma unroll 8
    for(int d=0;d<64;d++){
        float w=shw[d][tx];
        #pragma unroll
        for(int r=0;r<8;r++) acc[r]+=sh[ty+r*4][d]*w;
    }
    #pragma unroll
    for(int r=0;r<8;r++) atomicAdd(&g_agg[i][ty+r*4][e], acc[r]);
}

// ======== kernel 7: E/G accumulation (1296 single-tile blocks) ========
__global__ void k_eg(const float* __restrict__ WE, const float* __restrict__ WEb,
                     const float* __restrict__ Wh, const float* __restrict__ Whb,
                     const float* __restrict__ Wqc, const float* __restrict__ Wqcb){
    __shared__ float sh[32][64];
    __shared__ float shw[64][64];
    int blk=blockIdx.x;
    int i = blk/432; int rem=blk%432;
    int et = rem/36; int rem2=rem%36;
    int seg = rem2/12; int kc = rem2%12;
    int tx=threadIdx.x&63, ty=threadIdx.x>>6;
    int e=et*64+tx;
    int dbase=kc*64;
    const float* W  = (seg==0)? WE : (seg==1)? Wh : Wqc;
    const float* src = (seg==2)? &g_Q0[i][0][0] : &g_agg[i][0][0];
    float* dst = (seg==0)? &g_E[i][0][0] : &g_G[i][0][0];
    for(int q=threadIdx.x;q<512;q+=256){
        int bb=q>>4, dd4=q&15;
        ((float4*)sh[bb])[dd4] = ((const float4*)(src + (size_t)bb*Dd + dbase))[dd4];
    }
    for(int q=threadIdx.x;q<1024;q+=256){
        int rr=q>>4, cc=q&15;
        ((float4*)shw[rr])[cc] =
            ((const float4*)(W + ((size_t)i*Dd + dbase+rr)*Dd + et*64))[cc];
    }
    __syncthreads();
    float binit = 0.f;
    if(kc==0){
        if(seg==0) binit = WEb[i*Dd+e];
        else if(seg==1) binit = Whb[i*Dd+e]+Wqcb[i*Dd+e];
    }
    float acc[8];
    #pragma unroll
    for(int r=0;r<8;r++) acc[r]=binit;
    #pragma unroll 8
    for(int d=0;d<64;d++){
        float w=shw[d][tx];
        #pragma unroll
        for(int r=0;r<8;r++) acc[r]+=sh[ty+r*4][d]*w;
    }
    #pragma unroll
    for(int r=0;r<8;r++) atomicAdd(dst + (size_t)(ty+r*4)*Dd + e, acc[r]);
}

__device__ __forceinline__ float block_sum256(float v, float* sred){
    v = warp_sum(v);
    int wid=threadIdx.x>>5, lane=threadIdx.x&31;
    if(!lane) sred[wid]=v;
    __syncthreads();
    float t = (threadIdx.x<8)? sred[threadIdx.x] : 0.f;
    if(threadIdx.x<32){
        #pragma unroll
        for(int o=16;o>0;o>>=1) t += __shfl_xor_sync(0xffffffffu,t,o);
        if(threadIdx.x==0) sred[0]=t;
    }
    __syncthreads();
    float r = sred[0];
    __syncthreads();
    return r;
}

// ======== kernel 8: C = LN(relu(E))*LN(relu(G))  +  dout bias init ========
__global__ void k_lnprod(const float* __restrict__ lnEg, const float* __restrict__ lnEb,
                         const float* __restrict__ lnGg, const float* __restrict__ lnGb,
                         const float* __restrict__ out_b, float* __restrict__ dout){
    if(blockIdx.x >= Mm*Bb){
        int b = blockIdx.x - Mm*Bb;
        #pragma unroll
        for(int t=0;t<4;t++)
            dout[(size_t)b*Hh + t*256 + threadIdx.x] = out_b[t*256 + threadIdx.x];
        return;
    }
    __shared__ float sred[8];
    int i = blockIdx.x/Bb, b = blockIdx.x%Bb;
    float se=0.f, se2=0.f, sg=0.f, sg2=0.f;
    for(int d=threadIdx.x; d<Dd; d+=256){
        float ev=fmaxf(g_E[i][b][d],0.f), gv=fmaxf(g_G[i][b][d],0.f);
        se+=ev; se2+=ev*ev; sg+=gv; sg2+=gv*gv;
    }
    se  = block_sum256(se , sred);
    se2 = block_sum256(se2, sred);
    sg  = block_sum256(sg , sred);
    sg2 = block_sum256(sg2, sred);
    float mE = se/(float)Dd,  vE = se2/(float)Dd - mE*mE;
    float mG = sg/(float)Dd,  vG = sg2/(float)Dd - mG*mG;
    float rE = rsqrtf(vE + LNEPS), rG = rsqrtf(vG + LNEPS);
    for(int d=threadIdx.x; d<Dd; d+=256){
        float nE = (fmaxf(g_E[i][b][d],0.f)-mE)*rE*lnEg[i*Dd+d] + lnEb[i*Dd+d];
        float nG = (fmaxf(g_G[i][b][d],0.f)-mG)*rG*lnGg[i*Dd+d] + lnGb[i*Dd+d];
        g_C[i][b][d] = nE*nG;
    }
}

// ======== kernel 9: out += fused @ out_w (576 single-tile blocks) + kl ========
__global__ void k_out(const float* __restrict__ out_w, float* __restrict__ dout,
                      int write_kl){
    int blk=blockIdx.x;
    if(blk>=576){
        if(threadIdx.x==0 && write_kl) dout[Bb*Hh] = -0.5f*(float)(Mm-1)*g_kl;
        return;
    }
    __shared__ float sf[32][64];
    __shared__ float shw[64][64];
    int ht = blk/36;
    int kc = blk%36;
    int c0 = kc*64;
    int ii = c0/Dd; int dd = c0%Dd;
    int tx=threadIdx.x&63, ty=threadIdx.x>>6;
    int h = ht*64 + tx;
    for(int q=threadIdx.x;q<512;q+=256){
        int bb=q>>4, dd4=q&15;
        ((float4*)sf[bb])[dd4] = ((const float4*)(&g_C[ii][bb][dd]))[dd4];
    }
    for(int q=threadIdx.x;q<1024;q+=256){
        int rr=q>>4, cc=q&15;
        ((float4*)shw[rr])[cc] =
            ((const float4*)(out_w + ((size_t)(c0+rr))*Hh + ht*64))[cc];
    }
    __syncthreads();
    float acc[8];
    #pragma unroll
    for(int r=0;r<8;r++) acc[r]=0.f;
    #pragma unroll 8
    for(int d=0;d<64;d++){
        float w=shw[d][tx];
        #pragma unroll
        for(int r=0;r<8;r++) acc[r]+=sf[ty+r*4][d]*w;
    }
    #pragma unroll
    for(int r=0;r<8;r++) atomicAdd(&dout[(size_t)(ty+r*4)*Hh + h], acc[r]);
}

extern "C" void kernel_launch(void* const* d_in, const int* in_sizes, int n_in,
                              void* d_out, int out_size) {
    const float* feats = (const float*)d_in[0];
    const float* Wq    = (const float*)d_in[1];
    const float* bq    = (const float*)d_in[2];
    const float* Wk    = (const float*)d_in[3];
    const float* bk    = (const float*)d_in[4];
    const float* Wv    = (const float*)d_in[5];
    const float* bv    = (const float*)d_in[6];
    const float* pgq_w = (const float*)d_in[7];
    const float* pgq_b = (const float*)d_in[8];
    const float* pgk_w = (const float*)d_in[9];
    const float* pgk_b = (const float*)d_in[10];
    const float* mu_w  = (const float*)d_in[11];
    const float* mu_b  = (const float*)d_in[12];
    const float* lv_w  = (const float*)d_in[13];
    const float* lv_b  = (const float*)d_in[14];
    const float* dyn   = (const float*)d_in[15];
    const float* WE_w  = (const float*)d_in[16];
    const float* WE_b  = (const float*)d_in[17];
    const float* Wh_w  = (const float*)d_in[18];
    const float* Wh_b  = (const float*)d_in[19];
    const float* Wqc_w = (const float*)d_in[20];
    const float* Wqc_b = (const float*)d_in[21];
    const float* lnE_g = (const float*)d_in[22];
    const float* lnE_b = (const float*)d_in[23];
    const float* lnG_g = (const float*)d_in[24];
    const float* lnG_b = (const float*)d_in[25];
    const float* out_w = (const float*)d_in[26];
    const float* out_b = (const float*)d_in[27];
    const float* eps   = (const float*)d_in[28];
    float* dout = (float*)d_out;

    k_init<<<161,256>>>(bq, bk, mu_w, mu_b, lv_w, lv_b, pgq_w, pgq_b, pgk_w, pgk_b);
    k_q0<<<432,256>>>(feats, Wq, bq, mu_w, lv_w, pgq_w);
    k_qkvec<<<439,256>>>(Wk, bk, pgk_w, pgq_w, pgq_b);
    k_rowstats<<<768,256>>>(feats);
    k_attn2<<<288,256>>>(feats, eps, dyn);
    k_agg<<<864,256>>>(Wv, bv);
    k_eg<<<1296,256>>>(WE_w, WE_b, Wh_w, Wh_b, Wqc_w, Wqc_b);
    k_lnprod<<<128,256>>>(lnE_g, lnE_b, lnG_g, lnG_b, out_b, dout);
    k_out<<<577,256>>>(out_w, dout, (out_size > Bb*Hh) ? 1 : 0);
}

// round 13
// speedup vs baseline: 1.0189x; 1.0023x over previous
#include <cuda_runtime.h>
#include <math.h>

#define Mm 3
#define Bb 32
#define Ss 256
#define Dd 768
#define D4 192
#define Hh 1024
#define NPAIR 6
#define LNEPS 1e-5f
#define SCALE 0.036084391824351615f

// ---------------- scratch (__device__ globals) ------------
__device__ __align__(16) float g_wmu[Mm][Dd], g_wlv[Mm][Dd], g_wpq[Mm][Dd]; // atomic accum
__device__ float g_cmu[Mm], g_clv[Mm];
__device__ __align__(16) float g_wpk[Mm][Mm][Dd];                            // atomic accum
__device__ float g_cpk[Mm][Mm];
__device__ __align__(16) float g_Q0[Mm][Bb][Dd];          // atomic accum
__device__ __align__(16) float g_qkvec[Mm][Mm][Bb][Dd];   // atomic accum
__device__ float g_qbk[Mm][Mm][Bb];
__device__ float g_pq0[Mm][Bb];                            // pq logit at s=0
__device__ float g_mu[Mm][Bb][Ss], g_lv[Mm][Bb][Ss];
__device__ float g_kd[Mm][Mm][Bb][Ss];
__device__ float g_dotA[Mm][Mm][Bb][Ss];
__device__ __align__(16) float g_wf[Mm][Mm][Bb][Dd];
__device__ __align__(16) float g_agg[Mm][Bb][Dd];         // atomic accum
__device__ __align__(16) float g_E[Mm][Bb][Dd], g_G[Mm][Bb][Dd]; // atomic accum
__device__ __align__(16) float g_C[Mm][Bb][Dd];
__device__ float g_kl;

__device__ __forceinline__ float warp_sum(float v){
    #pragma unroll
    for(int o=16;o>0;o>>=1) v += __shfl_down_sync(0xffffffffu, v, o);
    return v;
}
__device__ __forceinline__ float sigmoidf(float x){ return 1.f/(1.f+expf(-x)); }
__device__ __forceinline__ float dot4(float4 a, float4 b){
    return a.x*b.x + a.y*b.y + a.z*b.z + a.w*b.w;
}

// ======== kernel 1: zero accumulators + scalar constants ========
__global__ void k_init(const float* __restrict__ bq, const float* __restrict__ bk,
                       const float* __restrict__ mu_w, const float* __restrict__ mu_b,
                       const float* __restrict__ lv_w, const float* __restrict__ lv_b,
                       const float* __restrict__ pgq_w, const float* __restrict__ pgq_b,
                       const float* __restrict__ pgk_w, const float* __restrict__ pgk_b){
    if(blockIdx.x < 160){
        int tid = blockIdx.x*256 + threadIdx.x;
        const int stride = 160*256;
        float* p;
        p=&g_Q0[0][0][0];       for(int i=tid;i<Mm*Bb*Dd;i+=stride)    p[i]=0.f;
        p=&g_qkvec[0][0][0][0]; for(int i=tid;i<Mm*Mm*Bb*Dd;i+=stride) p[i]=0.f;
        p=&g_agg[0][0][0];      for(int i=tid;i<Mm*Bb*Dd;i+=stride)    p[i]=0.f;
        p=&g_E[0][0][0];        for(int i=tid;i<Mm*Bb*Dd;i+=stride)    p[i]=0.f;
        p=&g_G[0][0][0];        for(int i=tid;i<Mm*Bb*Dd;i+=stride)    p[i]=0.f;
        p=&g_wmu[0][0];         for(int i=tid;i<Mm*Dd;i+=stride)       p[i]=0.f;
        p=&g_wlv[0][0];         for(int i=tid;i<Mm*Dd;i+=stride)       p[i]=0.f;
        p=&g_wpq[0][0];         for(int i=tid;i<Mm*Dd;i+=stride)       p[i]=0.f;
        p=&g_wpk[0][0][0];      for(int i=tid;i<Mm*Mm*Dd;i+=stride)    p[i]=0.f;
        if(tid==0) g_kl=0.f;
    } else {
        int wid=threadIdx.x>>5, lane=threadIdx.x&31;
        for(int t=wid;t<15;t+=8){
            if(t<6){
                int m=t/2, which=t%2;
                const float* wv = (which==0)? mu_w : lv_w;
                float a=0.f;
                for(int e=lane;e<Dd;e+=32) a += bq[m*Dd+e]*wv[m*Dd+e];
                a=warp_sum(a);
                if(!lane){
                    if(which==0) g_cmu[m]=a+mu_b[m];
                    else g_clv[m]=a+lv_b[m];
                }
            } else {
                int q=t-6; int i=q/3, j=q%3;
                float a=0.f;
                for(int e=lane;e<Dd;e+=32) a += bk[j*Dd+e]*pgk_w[i*Dd+e];
                a=warp_sum(a);
                if(!lane) g_cpk[i][j]=a+pgk_b[i];
            }
        }
    }
}

// ======== kernel 2: Q0 GEMM + wmu/wlv/wpq composites (Wq read once) ========
__global__ void k_q0(const float* __restrict__ feats, const float* __restrict__ Wq,
                     const float* __restrict__ bq,
                     const float* __restrict__ mu_w, const float* __restrict__ lv_w,
                     const float* __restrict__ pgq_w){
    __shared__ float sh[32][64];
    __shared__ float shw[64][64];
    int blk=blockIdx.x;
    int i=blk/144; int rem=blk%144; int et=rem/12; int kc=rem%12;
    int tx=threadIdx.x&63, ty=threadIdx.x>>6;
    int e=et*64+tx;
    int dbase=kc*64;
    for(int q=threadIdx.x;q<512;q+=256){
        int bb=q>>4, dd4=q&15;
        ((float4*)sh[bb])[dd4] =
            ((const float4*)(feats + (((size_t)i*Bb+bb)*Ss)*Dd + dbase))[dd4];
    }
    for(int q=threadIdx.x;q<1024;q+=256){
        int rr=q>>4, cc=q&15;
        ((float4*)shw[rr])[cc] =
            ((const float4*)(Wq + ((size_t)i*Dd + dbase+rr)*Dd + et*64))[cc];
    }
    __syncthreads();
    float acc[8];
    float binit=(kc==0)? bq[i*Dd+e] : 0.f;
    #pragma unroll
    for(int r=0;r<8;r++) acc[r]=binit;
    #pragma unroll 8
    for(int d=0;d<64;d++){
        float w=shw[d][tx];
        #pragma unroll
        for(int r=0;r<8;r++) acc[r]+=sh[ty+r*4][d]*w;
    }
    #pragma unroll
    for(int r=0;r<8;r++) atomicAdd(&g_Q0[i][ty+r*4][e], acc[r]);
    int wid=threadIdx.x>>5, lane=threadIdx.x&31;
    int ea=et*64+lane, eb=ea+32;
    float m0=mu_w[i*Dd+ea],  m1=mu_w[i*Dd+eb];
    float l0=lv_w[i*Dd+ea],  l1=lv_w[i*Dd+eb];
    float p0=pgq_w[i*Dd+ea], p1=pgq_w[i*Dd+eb];
    for(int rr=wid*8; rr<wid*8+8; rr++){
        float w0=shw[rr][lane], w1=shw[rr][lane+32];
        float a=w0*m0+w1*m1, b=w0*l0+w1*l1, c=w0*p0+w1*p1;
        a=warp_sum(a); b=warp_sum(b); c=warp_sum(c);
        if(!lane){
            atomicAdd(&g_wmu[i][dbase+rr],a);
            atomicAdd(&g_wlv[i][dbase+rr],b);
            atomicAdd(&g_wpq[i][dbase+rr],c);
        }
    }
}

// ======== kernel 3: qkvec GEMM + wpk composites (Wk read once) + qbk + pq0 ========
__global__ void k_qkvec(const float* __restrict__ Wk, const float* __restrict__ bk,
                        const float* __restrict__ pgk_w, const float* __restrict__ pgq_w,
                        const float* __restrict__ pgq_b){
    int blk=blockIdx.x;
    if(blk>=432){
        if(blk==438){
            // pq0[i][b] = Q0[i,b] . pgq_w[i] + pgq_b[i]   (96 dots)
            int wid=threadIdx.x>>5, lane=threadIdx.x&31;
            for(int t=wid;t<Mm*Bb;t+=8){
                int i=t/Bb, b=t%Bb;
                float a=0.f;
                for(int e=lane;e<Dd;e+=32) a += g_Q0[i][b][e]*pgq_w[i*Dd+e];
                a=warp_sum(a);
                if(!lane) g_pq0[i][b]=a+pgq_b[i];
            }
            return;
        }
        const int pi[6]={0,0,1,1,2,2}, pj[6]={1,2,0,2,0,1};
        int p=blk-432; int i=pi[p], j=pj[p];
        int wid=threadIdx.x>>5, lane=threadIdx.x&31;
        for(int b=wid;b<Bb;b+=8){
            float a=0.f;
            for(int e=lane;e<Dd;e+=32) a += bk[j*Dd+e]*g_Q0[i][b][e];
            a=warp_sum(a);
            if(!lane) g_qbk[i][j][b]=a;
        }
        return;
    }
    __shared__ float shq[64][64];
    __shared__ float shw[64][65];
    int j=blk/144; int rem=blk%144; int dt=rem/12; int kc=rem%12;
    int i0=(j==0)?1:0, i1=(j==2)?1:2;
    int tx=threadIdx.x&63, ty=threadIdx.x>>6;
    int d=dt*64+tx;
    int ebase=kc*64;
    for(int q=threadIdx.x;q<1024;q+=256){
        int rr=q>>4, cc=q&15;
        int ii=(rr<32)?i0:i1; int bb=rr&31;
        ((float4*)shq[rr])[cc] = ((const float4*)(&g_Q0[ii][bb][ebase]))[cc];
    }
    for(int q=threadIdx.x;q<1024;q+=256){
        int rr=q>>4, cc=q&15;
        float4 w4 = ((const float4*)(Wk + ((size_t)j*Dd + dt*64+rr)*Dd + ebase))[cc];
        shw[cc*4+0][rr]=w4.x; shw[cc*4+1][rr]=w4.y;
        shw[cc*4+2][rr]=w4.z; shw[cc*4+3][rr]=w4.w;
    }
    __syncthreads();
    float acc[16];
    #pragma unroll
    for(int r=0;r<16;r++) acc[r]=0.f;
    #pragma unroll 4
    for(int ee=0;ee<64;ee++){
        float w=shw[ee][tx];
        #pragma unroll
        for(int r=0;r<16;r++) acc[r]+=shq[ty+r*4][ee]*w;
    }
    #pragma unroll
    for(int r=0;r<16;r++){
        int vv=ty+r*4; int ii=(vv<32)?i0:i1; int bb=vv&31;
        atomicAdd(&g_qkvec[ii][j][bb][d], acc[r]);
    }
    int wid=threadIdx.x>>5, lane=threadIdx.x&31;
    float q00=pgk_w[0*Dd+ebase+lane], q01=pgk_w[0*Dd+ebase+lane+32];
    float q10=pgk_w[1*Dd+ebase+lane], q11=pgk_w[1*Dd+ebase+lane+32];
    float q20=pgk_w[2*Dd+ebase+lane], q21=pgk_w[2*Dd+ebase+lane+32];
    for(int rr=wid*8; rr<wid*8+8; rr++){
        float w0=shw[lane][rr], w1=shw[lane+32][rr];
        float a=w0*q00+w1*q01, b=w0*q10+w1*q11, c=w0*q20+w1*q21;
        a=warp_sum(a); b=warp_sum(b); c=warp_sum(c);
        if(!lane){
            atomicAdd(&g_wpk[0][j][dt*64+rr],a);
            atomicAdd(&g_wpk[1][j][dt*64+rr],b);
            atomicAdd(&g_wpk[2][j][dt*64+rr],c);
        }
    }
}

// ======== kernel 4: FUSED row stats + attention dots + kl (single feats pass) ========
// 768 blocks: (m, b, s-chunk of 32). 4 rows/warp, 6 dot-vectors (pqb dropped).
__global__ void __launch_bounds__(256, 3) k_rowstats(const float* __restrict__ feats){
    __shared__ float4 sw4[6][D4];
    __shared__ float skl[8];
    int blk=blockIdx.x;
    int m  = blk/256;
    int b  = (blk/8)%Bb;
    int sc = blk%8;
    int i0=(m==0)?1:0, i1=(m==2)?1:2;
    for(int d=threadIdx.x; d<D4; d+=256){
        sw4[0][d]=((const float4*)g_wmu[m])[d];
        sw4[1][d]=((const float4*)g_wlv[m])[d];
        sw4[2][d]=((const float4*)g_wpk[i0][m])[d];
        sw4[3][d]=((const float4*)g_wpk[i1][m])[d];
        sw4[4][d]=((const float4*)g_qkvec[i0][m][b])[d];
        sw4[5][d]=((const float4*)g_qkvec[i1][m][b])[d];
    }
    __syncthreads();
    int wid=threadIdx.x>>5, lane=threadIdx.x&31;
    const float* base = feats + ((size_t)m*Bb+b)*Ss*Dd;
    int s0 = sc*32 + wid*4;
    const float4* f0=(const float4*)(base + (size_t)s0*Dd);
    const float4* f1=f0+D4;
    const float4* f2=f1+D4;
    const float4* f3=f2+D4;
    float a[6][4];
    #pragma unroll
    for(int v=0;v<6;v++){
        a[v][0]=0.f; a[v][1]=0.f; a[v][2]=0.f; a[v][3]=0.f;
    }
    for(int d=lane; d<D4; d+=32){
        float4 x0=f0[d], x1=f1[d], x2=f2[d], x3=f3[d];
        #pragma unroll
        for(int v=0;v<6;v++){
            float4 w=sw4[v][d];
            a[v][0]+=dot4(x0,w);
            a[v][1]+=dot4(x1,w);
            a[v][2]+=dot4(x2,w);
            a[v][3]+=dot4(x3,w);
        }
    }
    #pragma unroll
    for(int v=0;v<6;v++){
        #pragma unroll
        for(int r=0;r<4;r++) a[v][r]=warp_sum(a[v][r]);
    }
    if(!lane){
        float qb0=g_qbk[i0][m][b], qb1=g_qbk[i1][m][b];
        float klacc=0.f;
        #pragma unroll
        for(int r=0;r<4;r++){
            int s = s0 + r;
            float mu=a[0][r]+g_cmu[m], lv=a[1][r]+g_clv[m];
            g_mu[m][b][s]=mu; g_lv[m][b][s]=lv;
            g_kd[i0][m][b][s]=a[2][r]+g_cpk[i0][m];
            g_kd[i1][m][b][s]=a[3][r]+g_cpk[i1][m];
            g_dotA[i0][m][b][s]=a[4][r]+qb0;
            g_dotA[i1][m][b][s]=a[5][r]+qb1;
            klacc += 1.f + lv - mu*mu - expf(lv);
        }
        skl[wid]=klacc;
    }
    __syncthreads();
    if(threadIdx.x==0){
        float t=0.f;
        #pragma unroll
        for(int w=0;w<8;w++) t+=skl[w];
        atomicAdd(&g_kl, t);
    }
}

// ======== kernel 5: gates + fused dual softmax + weighted feats sums (288 blocks) ========
__global__ void k_attn2(const float* __restrict__ feats, const float* __restrict__ eps,
                        const float* __restrict__ dyn){
    __shared__ float w0[Ss], w1[Ss];
    __shared__ float4 sr0[4][64], sr1[4][64];
    __shared__ float2 sred2[8];
    __shared__ float spq0, spq1;
    __shared__ float2 sscal2;
    int blk=blockIdx.x;
    int j  = blk/96;
    int b  = (blk/3)%Bb;
    int dc = blk%3;
    int i0=(j==0)?1:0, i1=(j==2)?1:2;
    int cnt0=(j<i0)? j : j-1;
    int cnt1=(j<i1)? j : j-1;
    int k=threadIdx.x;
    int wid=k>>5, lane=k&31;
    float dynv=dyn[0];
    float mu0=g_mu[i0][b][k], lv0=g_lv[i0][b][k];
    float e0 = eps[(((size_t)i0*(Mm-1)+cnt0)*Bb + b)*Ss + k];
    float gk0 = sigmoidf(mu0 + dynv*expf(0.5f*lv0)*e0);
    float pk0 = sigmoidf(g_kd[i0][j][b][k]) * gk0;
    float mu1=g_mu[i1][b][k], lv1=g_lv[i1][b][k];
    float e1 = eps[(((size_t)i1*(Mm-1)+cnt1)*Bb + b)*Ss + k];
    float gk1 = sigmoidf(mu1 + dynv*expf(0.5f*lv1)*e1);
    float pk1 = sigmoidf(g_kd[i1][j][b][k]) * gk1;
    if(k==0){
        spq0 = sigmoidf(g_pq0[i0][b]) * gk0;
        spq1 = sigmoidf(g_pq0[i1][b]) * gk1;
    }
    __syncthreads();
    float l0 = g_dotA[i0][j][b][k]*SCALE*spq0*pk0;
    float l1 = g_dotA[i1][j][b][k]*SCALE*spq1*pk1;
    // fused dual max-reduction
    {
        float mx0=l0, mx1=l1;
        #pragma unroll
        for(int o=16;o>0;o>>=1){
            mx0=fmaxf(mx0,__shfl_xor_sync(0xffffffffu,mx0,o));
            mx1=fmaxf(mx1,__shfl_xor_sync(0xffffffffu,mx1,o));
        }
        if(!lane) sred2[wid]=make_float2(mx0,mx1);
        __syncthreads();
        if(threadIdx.x==0){
            float t0=sred2[0].x, t1=sred2[0].y;
            #pragma unroll
            for(int w=1;w<8;w++){ t0=fmaxf(t0,sred2[w].x); t1=fmaxf(t1,sred2[w].y); }
            sscal2=make_float2(t0,t1);
        }
        __syncthreads();
    }
    float ex0=expf(l0-sscal2.x), ex1=expf(l1-sscal2.y);
    // fused dual sum-reduction
    {
        float sm0=ex0, sm1=ex1;
        #pragma unroll
        for(int o=16;o>0;o>>=1){
            sm0+=__shfl_xor_sync(0xffffffffu,sm0,o);
            sm1+=__shfl_xor_sync(0xffffffffu,sm1,o);
        }
        if(!lane) sred2[wid]=make_float2(sm0,sm1);
        __syncthreads();
        if(threadIdx.x==0){
            float t0=0.f, t1=0.f;
            #pragma unroll
            for(int w=0;w<8;w++){ t0+=sred2[w].x; t1+=sred2[w].y; }
            sscal2=make_float2(t0,t1);
        }
        __syncthreads();
    }
    w0[k]=ex0/sscal2.x;
    w1[k]=ex1/sscal2.y;
    __syncthreads();
    // weighted sum: thread=(kq,d4); float4 over 64-k chunk
    int d4 = threadIdx.x&63, kq = threadIdx.x>>6;
    const float4* f4 = (const float4*)(feats + (((size_t)j*Bb+b)*Ss)*Dd);
    int col = dc*64 + d4;
    float4 a0=make_float4(0.f,0.f,0.f,0.f), a1=a0;
    int kst=kq*64;
    #pragma unroll 8
    for(int kk=kst;kk<kst+64;kk++){
        float4 f = f4[(size_t)kk*D4 + col];
        float x0=w0[kk], x1=w1[kk];
        a0.x+=x0*f.x; a0.y+=x0*f.y; a0.z+=x0*f.z; a0.w+=x0*f.w;
        a1.x+=x1*f.x; a1.y+=x1*f.y; a1.z+=x1*f.z; a1.w+=x1*f.w;
    }
    sr0[kq][d4]=a0; sr1[kq][d4]=a1;
    __syncthreads();
    if(threadIdx.x<64){
        int d=threadIdx.x;
        float4 t0=sr0[0][d], t1=sr0[1][d], t2=sr0[2][d], t3=sr0[3][d];
        float4 u0=sr1[0][d], u1=sr1[1][d], u2=sr1[2][d], u3=sr1[3][d];
        float4 s0=make_float4(t0.x+t1.x+t2.x+t3.x, t0.y+t1.y+t2.y+t3.y,
                              t0.z+t1.z+t2.z+t3.z, t0.w+t1.w+t2.w+t3.w);
        float4 s1=make_float4(u0.x+u1.x+u2.x+u3.x, u0.y+u1.y+u2.y+u3.y,
                              u0.z+u1.z+u2.z+u3.z, u0.w+u1.w+u2.w+u3.w);
        ((float4*)&g_wf[i0][j][b][dc*256])[d] = s0;
        ((float4*)&g_wf[i1][j][b][dc*256])[d] = s1;
    }
}

// ======== kernel 6: agg += wf @ Wv (864 single-tile blocks) ========
__global__ void k_agg(const float* __restrict__ Wv, const float* __restrict__ bv){
    __shared__ float sh[32][64];
    __shared__ float shw[64][64];
    int blk=blockIdx.x;
    int i = blk/288; int rem=blk%288;
    int et = rem/24; int rem2=rem%24;
    int jj = rem2/12; int kc = rem2%12;
    int j0=(i==0)?1:0, j1=(i==2)?1:2;
    int j = jj? j1 : j0;
    int tx=threadIdx.x&63, ty=threadIdx.x>>6;
    int e=et*64+tx;
    int dbase=kc*64;
    for(int q=threadIdx.x;q<512;q+=256){
        int bb=q>>4, dd4=q&15;
        ((float4*)sh[bb])[dd4] = ((const float4*)(&g_wf[i][j][bb][dbase]))[dd4];
    }
    for(int q=threadIdx.x;q<1024;q+=256){
        int rr=q>>4, cc=q&15;
        ((float4*)shw[rr])[cc] =
            ((const float4*)(Wv + ((size_t)j*Dd + dbase+rr)*Dd + et*64))[cc];
    }
    __syncthreads();
    float acc[8];
    float binit = (kc==0)? bv[j*Dd+e] : 0.f;
    #pragma unroll
    for(int r=0;r<8;r++) acc[r]=binit;
    #pragma unroll 8
    for(int d=0;d<64;d++){
        float w=shw[d][tx];
        #pragma unroll
        for(int r=0;r<8;r++) acc[r]+=sh[ty+r*4][d]*w;
    }
    #pragma unroll
    for(int r=0;r<8;r++) atomicAdd(&g_agg[i][ty+r*4][e], acc[r]);
}

// ======== kernel 7: E/G accumulation (1296 single-tile blocks) ========
__global__ void k_eg(const float* __restrict__ WE, const float* __restrict__ WEb,
                     const float* __restrict__ Wh, const float* __restrict__ Whb,
                     const float* __restrict__ Wqc, const float* __restrict__ Wqcb){
    __shared__ float sh[32][64];
    __shared__ float shw[64][64];
    int blk=blockIdx.x;
    int i = blk/432; int rem=blk%432;
    int et = rem/36; int rem2=rem%36;
    int seg = rem2/12; int kc = rem2%12;
    int tx=threadIdx.x&63, ty=threadIdx.x>>6;
    int e=et*64+tx;
    int dbase=kc*64;
    const float* W  = (seg==0)? WE : (seg==1)? Wh : Wqc;
    const float* src = (seg==2)? &g_Q0[i][0][0] : &g_agg[i][0][0];
    float* dst = (seg==0)? &g_E[i][0][0] : &g_G[i][0][0];
    for(int q=threadIdx.x;q<512;q+=256){
        int bb=q>>4, dd4=q&15;
        ((float4*)sh[bb])[dd4] = ((const float4*)(src + (size_t)bb*Dd + dbase))[dd4];
    }
    for(int q=threadIdx.x;q<1024;q+=256){
        int rr=q>>4, cc=q&15;
        ((float4*)shw[rr])[cc] =
            ((const float4*)(W + ((size_t)i*Dd + dbase+rr)*Dd + et*64))[cc];
    }
    __syncthreads();
    float binit = 0.f;
    if(kc==0){
        if(seg==0) binit = WEb[i*Dd+e];
        else if(seg==1) binit = Whb[i*Dd+e]+Wqcb[i*Dd+e];
    }
    float acc[8];
    #pragma unroll
    for(int r=0;r<8;r++) acc[r]=binit;
    #pragma unroll 8
    for(int d=0;d<64;d++){
        float w=shw[d][tx];
        #pragma unroll
        for(int r=0;r<8;r++) acc[r]+=sh[ty+r*4][d]*w;
    }
    #pragma unroll
    for(int r=0;r<8;r++) atomicAdd(dst + (size_t)(ty+r*4)*Dd + e, acc[r]);
}

__device__ __forceinline__ float block_sum256(float v, float* sred){
    v = warp_sum(v);
    int wid=threadIdx.x>>5, lane=threadIdx.x&31;
    if(!lane) sred[wid]=v;
    __syncthreads();
    float t = (threadIdx.x<8)? sred[threadIdx.x] : 0.f;
    if(threadIdx.x<32){
        #pragma unroll
        for(int o=16;o>0;o>>=1) t += __shfl_xor_sync(0xffffffffu,t,o);
        if(threadIdx.x==0) sred[0]=t;
    }
    __syncthreads();
    float r = sred[0];
    __syncthreads();
    return r;
}

// ======== kernel 8: C = LN(relu(E))*LN(relu(G))  +  dout bias init ========
__global__ void k_lnprod(const float* __restrict__ lnEg, const float* __restrict__ lnEb,
                         const float* __restrict__ lnGg, const float* __restrict__ lnGb,
                         const float* __restrict__ out_b, float* __restrict__ dout){
    if(blockIdx.x >= Mm*Bb){
        int b = blockIdx.x - Mm*Bb;
        #pragma unroll
        for(int t=0;t<4;t++)
            dout[(size_t)b*Hh + t*256 + threadIdx.x] = out_b[t*256 + threadIdx.x];
        return;
    }
    __shared__ float sred[8];
    int i = blockIdx.x/Bb, b = blockIdx.x%Bb;
    float se=0.f, se2=0.f, sg=0.f, sg2=0.f;
    for(int d=threadIdx.x; d<Dd; d+=256){
        float ev=fmaxf(g_E[i][b][d],0.f), gv=fmaxf(g_G[i][b][d],0.f);
        se+=ev; se2+=ev*ev; sg+=gv; sg2+=gv*gv;
    }
    se  = block_sum256(se , sred);
    se2 = block_sum256(se2, sred);
    sg  = block_sum256(sg , sred);
    sg2 = block_sum256(sg2, sred);
    float mE = se/(float)Dd,  vE = se2/(float)Dd - mE*mE;
    float mG = sg/(float)Dd,  vG = sg2/(float)Dd - mG*mG;
    float rE = rsqrtf(vE + LNEPS), rG = rsqrtf(vG + LNEPS);
    for(int d=threadIdx.x; d<Dd; d+=256){
        float nE = (fmaxf(g_E[i][b][d],0.f)-mE)*rE*lnEg[i*Dd+d] + lnEb[i*Dd+d];
        float nG = (fmaxf(g_G[i][b][d],0.f)-mG)*rG*lnGg[i*Dd+d] + lnGb[i*Dd+d];
        g_C[i][b][d] = nE*nG;
    }
}

// ======== kernel 9: out += fused @ out_w (576 single-tile blocks) + kl ========
__global__ void k_out(const float* __restrict__ out_w, float* __restrict__ dout,
                      int write_kl){
    int blk=blockIdx.x;
    if(blk>=576){
        if(threadIdx.x==0 && write_kl) dout[Bb*Hh] = -0.5f*(float)(Mm-1)*g_kl;
        return;
    }
    __shared__ float sf[32][64];
    __shared__ float shw[64][64];
    int ht = blk/36;
    int kc = blk%36;
    int c0 = kc*64;
    int ii = c0/Dd; int dd = c0%Dd;
    int tx=threadIdx.x&63, ty=threadIdx.x>>6;
    int h = ht*64 + tx;
    for(int q=threadIdx.x;q<512;q+=256){
        int bb=q>>4, dd4=q&15;
        ((float4*)sf[bb])[dd4] = ((const float4*)(&g_C[ii][bb][dd]))[dd4];
    }
    for(int q=threadIdx.x;q<1024;q+=256){
        int rr=q>>4, cc=q&15;
        ((float4*)shw[rr])[cc] =
            ((const float4*)(out_w + ((size_t)(c0+rr))*Hh + ht*64))[cc];
    }
    __syncthreads();
    float acc[8];
    #pragma unroll
    for(int r=0;r<8;r++) acc[r]=0.f;
    #pragma unroll 8
    for(int d=0;d<64;d++){
        float w=shw[d][tx];
        #pragma unroll
        for(int r=0;r<8;r++) acc[r]+=sf[ty+r*4][d]*w;
    }
    #pragma unroll
    for(int r=0;r<8;r++) atomicAdd(&dout[(size_t)(ty+r*4)*Hh + h], acc[r]);
}

extern "C" void kernel_launch(void* const* d_in, const int* in_sizes, int n_in,
                              void* d_out, int out_size) {
    const float* feats = (const float*)d_in[0];
    const float* Wq    = (const float*)d_in[1];
    const float* bq    = (const float*)d_in[2];
    const float* Wk    = (const float*)d_in[3];
    const float* bk    = (const float*)d_in[4];
    const float* Wv    = (const float*)d_in[5];
    const float* bv    = (const float*)d_in[6];
    const float* pgq_w = (const float*)d_in[7];
    const float* pgq_b = (const float*)d_in[8];
    const float* pgk_w = (const float*)d_in[9];
    const float* pgk_b = (const float*)d_in[10];
    const float* mu_w  = (const float*)d_in[11];
    const float* mu_b  = (const float*)d_in[12];
    const float* lv_w  = (const float*)d_in[13];
    const float* lv_b  = (const float*)d_in[14];
    const float* dyn   = (const float*)d_in[15];
    const float* WE_w  = (const float*)d_in[16];
    const float* WE_b  = (const float*)d_in[17];
    const float* Wh_w  = (const float*)d_in[18];
    const float* Wh_b  = (const float*)d_in[19];
    const float* Wqc_w = (const float*)d_in[20];
    const float* Wqc_b = (const float*)d_in[21];
    const float* lnE_g = (const float*)d_in[22];
    const float* lnE_b = (const float*)d_in[23];
    const float* lnG_g = (const float*)d_in[24];
    const float* lnG_b = (const float*)d_in[25];
    const float* out_w = (const float*)d_in[26];
    const float* out_b = (const float*)d_in[27];
    const float* eps   = (const float*)d_in[28];
    float* dout = (float*)d_out;

    k_init<<<161,256>>>(bq, bk, mu_w, mu_b, lv_w, lv_b, pgq_w, pgq_b, pgk_w, pgk_b);
    k_q0<<<432,256>>>(feats, Wq, bq, mu_w, lv_w, pgq_w);
    k_qkvec<<<439,256>>>(Wk, bk, pgk_w, pgq_w, pgq_b);
    k_rowstats<<<768,256>>>(feats);
    k_attn2<<<288,256>>>(feats, eps, dyn);
    k_agg<<<864,256>>>(Wv, bv);
    k_eg<<<1296,256>>>(WE_w, WE_b, Wh_w, Wh_b, Wqc_w, Wqc_b);
    k_lnprod<<<128,256>>>(lnE_g, lnE_b, lnG_g, lnG_b, out_b, dout);
    k_out<<<577,256>>>(out_w, dout, (out_size > Bb*Hh) ? 1 : 0);
}